// round 2
// baseline (speedup 1.0000x reference)
#include <cuda_runtime.h>
#include <cstdint>

#define BATCH   8
#define S_LEN   2048
#define EMB     512
#define HEADS   64
#define DK      8
#define NTOK    (BATCH * S_LEN)   // 16384

// Scrambled attention output (b, h*32 + s/64, (s%64)*8 + d), 33.5 MB scratch.
__device__ float g_Y[(size_t)NTOK * EMB];

// ---------------------------------------------------------------------------
// Kernel A: per-token quantum projection + head-axis attention.
// 4 tokens per 256-thread block; 64 threads per token; thread h owns row h.
// ---------------------------------------------------------------------------
__global__ __launch_bounds__(256, 2) void attn_kernel(const float* __restrict__ x,
                                                      const float* __restrict__ theta) {
    __shared__ float sproj[4][HEADS][DK];   // 8 KB

    const int tok_l = threadIdx.x >> 6;     // 0..3
    const int h     = threadIdx.x & 63;     // head row
    const int t     = (blockIdx.x << 2) + tok_l;
    const int b     = t >> 11;
    const int s     = t & 2047;

    const float4* xt  = (const float4*)(x + (size_t)t * EMB);
    const float4* th4 = (const float4*)theta;
    const float4 xa = xt[h * 2 + 0];
    const float4 xb = xt[h * 2 + 1];
    const float4 ta = th4[0];
    const float4 tb = th4[1];

    float p0 = cosf(xa.x + ta.x), p1 = cosf(xa.y + ta.y);
    float p2 = cosf(xa.z + ta.z), p3 = cosf(xa.w + ta.w);
    float p4 = cosf(xb.x + tb.x), p5 = cosf(xb.y + tb.y);
    float p6 = cosf(xb.z + tb.z), p7 = cosf(xb.w + tb.w);

    float4* sp = (float4*)&sproj[tok_l][h][0];
    sp[0] = make_float4(p0, p1, p2, p3);
    sp[1] = make_float4(p4, p5, p6, p7);
    __syncthreads();

    const float4* pj = (const float4*)&sproj[tok_l][0][0];

    // Pass 1: scores (unscaled dots) + running max
    float sc[64];
    float m = -1e30f;
#pragma unroll
    for (int g = 0; g < 64; ++g) {
        float4 qa = pj[g * 2 + 0];
        float4 qb = pj[g * 2 + 1];
        float d = fmaf(p0, qa.x, fmaf(p1, qa.y, fmaf(p2, qa.z, fmaf(p3, qa.w,
                  fmaf(p4, qb.x, fmaf(p5, qb.y, fmaf(p6, qb.z, p7 * qb.w)))))));
        sc[g] = d;
        m = fmaxf(m, d);
    }

    // scale = 1/sqrt(8) * log2(e)  (fold softmax scale into exp2)
    const float SCALE = 0.35355339059327373f * 1.4426950408889634f;

    // Pass 2: softmax weights + weighted sum of proj rows
    float sum = 0.f;
    float a0 = 0.f, a1 = 0.f, a2 = 0.f, a3 = 0.f;
    float a4 = 0.f, a5 = 0.f, a6 = 0.f, a7 = 0.f;
#pragma unroll
    for (int g = 0; g < 64; ++g) {
        float w = exp2f((sc[g] - m) * SCALE);
        sum += w;
        float4 qa = pj[g * 2 + 0];
        float4 qb = pj[g * 2 + 1];
        a0 = fmaf(w, qa.x, a0); a1 = fmaf(w, qa.y, a1);
        a2 = fmaf(w, qa.z, a2); a3 = fmaf(w, qa.w, a3);
        a4 = fmaf(w, qb.x, a4); a5 = fmaf(w, qb.y, a5);
        a6 = fmaf(w, qb.z, a6); a7 = fmaf(w, qb.w, a7);
    }
    const float inv = 1.0f / sum;

    // Scrambled destination: row = h*32 + s/64, col = (s%64)*8
    const size_t row = (size_t)b * 2048 + (size_t)h * 32 + (s >> 6);
    float* dst = g_Y + row * EMB + ((s & 63) << 3);
    ((float4*)dst)[0] = make_float4(a0 * inv, a1 * inv, a2 * inv, a3 * inv);
    ((float4*)dst)[1] = make_float4(a4 * inv, a5 * inv, a6 * inv, a7 * inv);
}

// ---------------------------------------------------------------------------
// Kernel B: out[16384,512] = Y @ W^T + bias, tf32 mma.sync m16n8k8.
// 128x128x32 tiles, 256 threads (8 warps, 4x2), warp tile 32x64.
// ---------------------------------------------------------------------------
__device__ __forceinline__ uint32_t f2tf(float f) {
    uint32_t r;
    asm("cvt.rna.tf32.f32 %0, %1;" : "=r"(r) : "f"(f));
    return r;
}

__global__ __launch_bounds__(256, 1) void gemm_kernel(const float* __restrict__ W,
                                                      const float* __restrict__ bias,
                                                      float* __restrict__ out) {
    __shared__ uint32_t As[128][36];   // +4 pad: fragment LDS bank = 4*gID + tig (conflict-free)
    __shared__ uint32_t Bs[128][36];

    const int tid  = threadIdx.x;
    const int bm   = blockIdx.x;       // 0..127
    const int bn   = blockIdx.y;       // 0..3
    const int warp = tid >> 5;
    const int lane = tid & 31;
    const int wm   = warp >> 1;        // 0..3
    const int wn   = warp & 1;         // 0..1
    const int gID  = lane >> 2;        // 0..7
    const int tig  = lane & 3;         // 0..3

    float c[2][8][4];
#pragma unroll
    for (int mi = 0; mi < 2; ++mi)
#pragma unroll
        for (int ni = 0; ni < 8; ++ni)
#pragma unroll
            for (int k = 0; k < 4; ++k) c[mi][ni][k] = 0.f;

    const int lr = tid >> 3;           // 0..31 (row within 32-row pass)
    const int lc = (tid & 7) << 2;     // 0,4,...,28

    const float* Abase = g_Y + ((size_t)bm * 128 + lr) * EMB + lc;
    const float* Bbase = W   + ((size_t)bn * 128 + lr) * EMB + lc;

    for (int kt = 0; kt < EMB; kt += 32) {
#pragma unroll
        for (int ppp = 0; ppp < 4; ++ppp) {
            float4 va = *(const float4*)(Abase + (size_t)ppp * 32 * EMB + kt);
            uint32_t* da = &As[lr + ppp * 32][lc];
            da[0] = f2tf(va.x); da[1] = f2tf(va.y); da[2] = f2tf(va.z); da[3] = f2tf(va.w);
            float4 vb = *(const float4*)(Bbase + (size_t)ppp * 32 * EMB + kt);
            uint32_t* db = &Bs[lr + ppp * 32][lc];
            db[0] = f2tf(vb.x); db[1] = f2tf(vb.y); db[2] = f2tf(vb.z); db[3] = f2tf(vb.w);
        }
        __syncthreads();

#pragma unroll
        for (int ks = 0; ks < 32; ks += 8) {
            uint32_t a[2][4];
#pragma unroll
            for (int mi = 0; mi < 2; ++mi) {
                int mrow = wm * 32 + mi * 16;
                a[mi][0] = As[mrow + gID    ][ks + tig    ];
                a[mi][1] = As[mrow + gID + 8][ks + tig    ];
                a[mi][2] = As[mrow + gID    ][ks + tig + 4];
                a[mi][3] = As[mrow + gID + 8][ks + tig + 4];
            }
#pragma unroll
            for (int ni = 0; ni < 8; ++ni) {
                int nrow = wn * 64 + ni * 8;
                uint32_t b0 = Bs[nrow + gID][ks + tig    ];
                uint32_t b1 = Bs[nrow + gID][ks + tig + 4];
#pragma unroll
                for (int mi = 0; mi < 2; ++mi) {
                    asm volatile(
                        "mma.sync.aligned.m16n8k8.row.col.f32.tf32.tf32.f32 "
                        "{%0,%1,%2,%3}, {%4,%5,%6,%7}, {%8,%9}, {%0,%1,%2,%3};"
                        : "+f"(c[mi][ni][0]), "+f"(c[mi][ni][1]),
                          "+f"(c[mi][ni][2]), "+f"(c[mi][ni][3])
                        : "r"(a[mi][0]), "r"(a[mi][1]), "r"(a[mi][2]), "r"(a[mi][3]),
                          "r"(b0), "r"(b1));
                }
            }
        }
        __syncthreads();
    }

    // Epilogue: +bias, float2 stores
#pragma unroll
    for (int mi = 0; mi < 2; ++mi) {
        int row = bm * 128 + wm * 32 + mi * 16 + gID;
#pragma unroll
        for (int ni = 0; ni < 8; ++ni) {
            int col = bn * 128 + wn * 64 + ni * 8 + (tig << 1);
            float b0v = bias[col], b1v = bias[col + 1];
            float2 v0 = make_float2(c[mi][ni][0] + b0v, c[mi][ni][1] + b1v);
            float2 v1 = make_float2(c[mi][ni][2] + b0v, c[mi][ni][3] + b1v);
            *(float2*)(out + (size_t)row * EMB + col)       = v0;
            *(float2*)(out + (size_t)(row + 8) * EMB + col) = v1;
        }
    }
}

// ---------------------------------------------------------------------------
extern "C" void kernel_launch(void* const* d_in, const int* in_sizes, int n_in,
                              void* d_out, int out_size) {
    const float* x     = (const float*)d_in[0];   // (8, 2048, 512) f32
    const float* theta = (const float*)d_in[1];   // (8,) f32
    const float* Wc    = (const float*)d_in[2];   // (512, 512) f32
    const float* bc    = (const float*)d_in[3];   // (512,) f32
    float* out = (float*)d_out;                   // (8, 2048, 512) f32

    attn_kernel<<<NTOK / 4, 256>>>(x, theta);

    dim3 grid(NTOK / 128, EMB / 128);
    gemm_kernel<<<grid, 256>>>(Wc, bc, out);
}

// round 3
// speedup vs baseline: 7.2122x; 7.2122x over previous
#include <cuda_runtime.h>
#include <cstdint>

#define BATCH   8
#define S_LEN   2048
#define EMB     512
#define HEADS   64
#define DK      8
#define NTOK    (BATCH * S_LEN)   // 16384

// Scrambled attention output (b, h*32 + s/64, (s%64)*8 + d), 33.5 MB scratch.
__device__ float g_Y[(size_t)NTOK * EMB];

// ---------------------------------------------------------------------------
// Packed f32x2 helpers (sm_103a; ptxas won't auto-fuse — must be inline PTX)
// ---------------------------------------------------------------------------
typedef unsigned long long u64;

__device__ __forceinline__ u64 pk2(float lo, float hi) {
    u64 r; asm("mov.b64 %0, {%1, %2};" : "=l"(r) : "f"(lo), "f"(hi)); return r;
}
__device__ __forceinline__ void upk2(u64 v, float& lo, float& hi) {
    asm("mov.b64 {%0, %1}, %2;" : "=f"(lo), "=f"(hi) : "l"(v));
}
__device__ __forceinline__ u64 fma2(u64 a, u64 b, u64 c) {
    u64 d; asm("fma.rn.f32x2 %0, %1, %2, %3;" : "=l"(d) : "l"(a), "l"(b), "l"(c)); return d;
}
__device__ __forceinline__ u64 mul2(u64 a, u64 b) {
    u64 d; asm("mul.rn.f32x2 %0, %1, %2;" : "=l"(d) : "l"(a), "l"(b)); return d;
}
__device__ __forceinline__ float ex2a(float x) {
    float r; asm("ex2.approx.f32 %0, %1;" : "=f"(r) : "f"(x)); return r;
}

// ---------------------------------------------------------------------------
// Kernel A: quantum projection + head-axis attention, SINGLE-PASS softmax.
// |score/sqrt(8)| <= 2.83, so no max-subtraction is needed: exp2 arg in
// [-4.1, 4.1] — no overflow possible. No score array -> no spills.
// 4 tokens per 256-thread block; thread h owns head row h of its token.
// ---------------------------------------------------------------------------
__global__ __launch_bounds__(256) void attn_kernel(const float* __restrict__ x,
                                                   const float* __restrict__ theta) {
    __shared__ __align__(16) float sproj[4][HEADS][DK];   // 8 KB

    const int tok_l = threadIdx.x >> 6;     // 0..3
    const int h     = threadIdx.x & 63;     // head row
    const int t     = (blockIdx.x << 2) + tok_l;
    const int b     = t >> 11;
    const int s     = t & 2047;

    const float4* xt  = (const float4*)(x + (size_t)t * EMB);
    const float4* th4 = (const float4*)theta;
    const float4 xa = xt[h * 2 + 0];
    const float4 xb = xt[h * 2 + 1];
    const float4 ta = th4[0];
    const float4 tb = th4[1];

    float p0 = cosf(xa.x + ta.x), p1 = cosf(xa.y + ta.y);
    float p2 = cosf(xa.z + ta.z), p3 = cosf(xa.w + ta.w);
    float p4 = cosf(xb.x + tb.x), p5 = cosf(xb.y + tb.y);
    float p6 = cosf(xb.z + tb.z), p7 = cosf(xb.w + tb.w);

    float4* sp = (float4*)&sproj[tok_l][h][0];
    sp[0] = make_float4(p0, p1, p2, p3);
    sp[1] = make_float4(p4, p5, p6, p7);
    __syncthreads();

    // Packed own-row proj
    const u64 P01 = pk2(p0, p1), P23 = pk2(p2, p3);
    const u64 P45 = pk2(p4, p5), P67 = pk2(p6, p7);

    // scale = 1/sqrt(8) * log2(e)  (softmax scale folded into exp2)
    const float SCALE = 0.35355339059327373f * 1.4426950408889634f;

    const ulonglong2* pj = (const ulonglong2*)&sproj[tok_l][0][0];

    float sum = 0.f;
    u64 A01 = 0, A23 = 0, A45 = 0, A67 = 0;  // bit pattern of (0.f,0.f)

#pragma unroll 16
    for (int g = 0; g < 64; ++g) {
        // 16B broadcast loads of row g (uniform address within warp)
        ulonglong2 qa = pj[g * 2 + 0];   // q01, q23
        ulonglong2 qb = pj[g * 2 + 1];   // q45, q67

        // Packed dot product: 4 f32x2 ops = 8 FMAs
        u64 d2 = mul2(P01, qa.x);
        d2 = fma2(P23, qa.y, d2);
        d2 = fma2(P45, qb.x, d2);
        d2 = fma2(P67, qb.y, d2);
        float dlo, dhi; upk2(d2, dlo, dhi);

        float w = ex2a((dlo + dhi) * SCALE);
        sum += w;

        u64 ww = pk2(w, w);
        A01 = fma2(ww, qa.x, A01);
        A23 = fma2(ww, qa.y, A23);
        A45 = fma2(ww, qb.x, A45);
        A67 = fma2(ww, qb.y, A67);
    }

    const float inv = 1.0f / sum;
    float a0, a1, a2, a3, a4, a5, a6, a7;
    upk2(A01, a0, a1); upk2(A23, a2, a3);
    upk2(A45, a4, a5); upk2(A67, a6, a7);

    // Scrambled destination: row = b*2048 + h*32 + s/64, col = (s%64)*8
    const size_t row = (size_t)b * 2048 + (size_t)h * 32 + (s >> 6);
    float* dst = g_Y + row * EMB + ((s & 63) << 3);
    ((float4*)dst)[0] = make_float4(a0 * inv, a1 * inv, a2 * inv, a3 * inv);
    ((float4*)dst)[1] = make_float4(a4 * inv, a5 * inv, a6 * inv, a7 * inv);
}

// ---------------------------------------------------------------------------
// Kernel B: out[16384,512] = Y @ W^T + bias, tf32 mma.sync m16n8k8.
// (unchanged from R1 — known correct at 94.7us; targeted next round)
// ---------------------------------------------------------------------------
__device__ __forceinline__ uint32_t f2tf(float f) {
    uint32_t r;
    asm("cvt.rna.tf32.f32 %0, %1;" : "=r"(r) : "f"(f));
    return r;
}

__global__ __launch_bounds__(256, 1) void gemm_kernel(const float* __restrict__ W,
                                                      const float* __restrict__ bias,
                                                      float* __restrict__ out) {
    __shared__ uint32_t As[128][36];
    __shared__ uint32_t Bs[128][36];

    const int tid  = threadIdx.x;
    const int bm   = blockIdx.x;
    const int bn   = blockIdx.y;
    const int warp = tid >> 5;
    const int lane = tid & 31;
    const int wm   = warp >> 1;
    const int wn   = warp & 1;
    const int gID  = lane >> 2;
    const int tig  = lane & 3;

    float c[2][8][4];
#pragma unroll
    for (int mi = 0; mi < 2; ++mi)
#pragma unroll
        for (int ni = 0; ni < 8; ++ni)
#pragma unroll
            for (int k = 0; k < 4; ++k) c[mi][ni][k] = 0.f;

    const int lr = tid >> 3;
    const int lc = (tid & 7) << 2;

    const float* Abase = g_Y + ((size_t)bm * 128 + lr) * EMB + lc;
    const float* Bbase = W   + ((size_t)bn * 128 + lr) * EMB + lc;

    for (int kt = 0; kt < EMB; kt += 32) {
#pragma unroll
        for (int ppp = 0; ppp < 4; ++ppp) {
            float4 va = *(const float4*)(Abase + (size_t)ppp * 32 * EMB + kt);
            uint32_t* da = &As[lr + ppp * 32][lc];
            da[0] = f2tf(va.x); da[1] = f2tf(va.y); da[2] = f2tf(va.z); da[3] = f2tf(va.w);
            float4 vb = *(const float4*)(Bbase + (size_t)ppp * 32 * EMB + kt);
            uint32_t* db = &Bs[lr + ppp * 32][lc];
            db[0] = f2tf(vb.x); db[1] = f2tf(vb.y); db[2] = f2tf(vb.z); db[3] = f2tf(vb.w);
        }
        __syncthreads();

#pragma unroll
        for (int ks = 0; ks < 32; ks += 8) {
            uint32_t a[2][4];
#pragma unroll
            for (int mi = 0; mi < 2; ++mi) {
                int mrow = wm * 32 + mi * 16;
                a[mi][0] = As[mrow + gID    ][ks + tig    ];
                a[mi][1] = As[mrow + gID + 8][ks + tig    ];
                a[mi][2] = As[mrow + gID    ][ks + tig + 4];
                a[mi][3] = As[mrow + gID + 8][ks + tig + 4];
            }
#pragma unroll
            for (int ni = 0; ni < 8; ++ni) {
                int nrow = wn * 64 + ni * 8;
                uint32_t b0 = Bs[nrow + gID][ks + tig    ];
                uint32_t b1 = Bs[nrow + gID][ks + tig + 4];
#pragma unroll
                for (int mi = 0; mi < 2; ++mi) {
                    asm volatile(
                        "mma.sync.aligned.m16n8k8.row.col.f32.tf32.tf32.f32 "
                        "{%0,%1,%2,%3}, {%4,%5,%6,%7}, {%8,%9}, {%0,%1,%2,%3};"
                        : "+f"(c[mi][ni][0]), "+f"(c[mi][ni][1]),
                          "+f"(c[mi][ni][2]), "+f"(c[mi][ni][3])
                        : "r"(a[mi][0]), "r"(a[mi][1]), "r"(a[mi][2]), "r"(a[mi][3]),
                          "r"(b0), "r"(b1));
                }
            }
        }
        __syncthreads();
    }

#pragma unroll
    for (int mi = 0; mi < 2; ++mi) {
        int row = bm * 128 + wm * 32 + mi * 16 + gID;
#pragma unroll
        for (int ni = 0; ni < 8; ++ni) {
            int col = bn * 128 + wn * 64 + ni * 8 + (tig << 1);
            float b0v = bias[col], b1v = bias[col + 1];
            float2 v0 = make_float2(c[mi][ni][0] + b0v, c[mi][ni][1] + b1v);
            float2 v1 = make_float2(c[mi][ni][2] + b0v, c[mi][ni][3] + b1v);
            *(float2*)(out + (size_t)row * EMB + col)       = v0;
            *(float2*)(out + (size_t)(row + 8) * EMB + col) = v1;
        }
    }
}

// ---------------------------------------------------------------------------
extern "C" void kernel_launch(void* const* d_in, const int* in_sizes, int n_in,
                              void* d_out, int out_size) {
    const float* x     = (const float*)d_in[0];   // (8, 2048, 512) f32
    const float* theta = (const float*)d_in[1];   // (8,) f32
    const float* Wc    = (const float*)d_in[2];   // (512, 512) f32
    const float* bc    = (const float*)d_in[3];   // (512,) f32
    float* out = (float*)d_out;                   // (8, 2048, 512) f32

    attn_kernel<<<NTOK / 4, 256>>>(x, theta);

    dim3 grid(NTOK / 128, EMB / 128);
    gemm_kernel<<<grid, 256>>>(Wc, bc, out);
}